// round 9
// baseline (speedup 1.0000x reference)
#include <cuda_runtime.h>
#include <cuda_fp16.h>
#include <math.h>
#include <stdint.h>

// Problem constants
#define N_TOK   131072      // 32 * 4096 tokens
#define DIM     64
#define KCODES  1024
#define TT      128         // tokens per CTA
#define CH      64          // codes per smem chunk
#define NCH     (KCODES / CH)   // 16
#define NB      (N_TOK / TT)    // 1024 CTAs
#define NTHREADS 256
#define XSTR    68          // padded fp32 x stride
#define WHSTR   72          // padded fp16 W stride (halves) -> 144B rows, 16B-mult

// Screen margin: must exceed 2 * worst-case |fp16_dist - fp32_dist|
// (<= 2*2e-4 = 4e-4 for this data). 1e-3 is safely above.
#define MARGIN  1e-3f

#define QCAP    4096        // candidate queue capacity

// smem layout (float offsets)
#define OFF_XS     0                     // 128*68        = 8704 floats
#define OFF_WH     8704                  // 2*64*72 half  = 4608 floats
#define OFF_WSQ    13312                 // 1024
#define OFF_XSQ    14336                 // 128
#define OFF_BEST   14464                 // 128 u64 = 256 floats (8B aligned)
#define OFF_QCNT   14720                 // 4
#define OFF_QUEUE  14724                 // 4096
#define OFF_FIDX   18820                 // 128
#define OFF_RED    18948                 // 256
#define SMEM_FLOATS 19204
#define SMEM_BYTES (SMEM_FLOATS * 4)

// Scratch
__device__ float  g_wsq[KCODES];
__device__ int    g_counts[KCODES];
__device__ float  g_part[NB];
__device__ __half g_wh[KCODES * DIM];    // fp16 codebook (prep-built)

__device__ __forceinline__ uint32_t smem_u32(const void* p) {
    uint32_t a;
    asm("{ .reg .u64 t; cvta.to.shared.u64 t, %1; cvt.u32.u64 %0, t; }"
        : "=r"(a) : "l"(p));
    return a;
}

// Pack two fp32 into one u32 holding half2 bits (RN conversion).
__device__ __forceinline__ uint32_t f2_to_h2_bits(float lo, float hi) {
    __half2 h = __floats2half2_rn(lo, hi);
    uint32_t u;
    u = (uint32_t)__half_as_ushort(__high2half(h)) << 16
      | (uint32_t)__half_as_ushort(__low2half(h));
    return u;
}

#define CP_ASYNC16(dst_u32, src_gptr) \
    asm volatile("cp.async.ca.shared.global [%0], [%1], 16;" \
                 :: "r"(dst_u32), "l"(src_gptr) : "memory")
#define CP_COMMIT() asm volatile("cp.async.commit_group;" ::: "memory")
#define CP_WAIT0()  asm volatile("cp.async.wait_group 0;"  ::: "memory")

// fp16 HMMA m16n8k16 (hardware path on sm_103; tf32 mma is FFMA-emulated)
__device__ __forceinline__ void mma_f16(float& c0, float& c1, float& c2, float& c3,
                                        uint32_t a0, uint32_t a1, uint32_t a2, uint32_t a3,
                                        uint32_t b0, uint32_t b1) {
    asm volatile(
        "mma.sync.aligned.m16n8k16.row.col.f32.f16.f16.f32 "
        "{%0,%1,%2,%3}, {%4,%5,%6,%7}, {%8,%9}, {%0,%1,%2,%3};"
        : "+f"(c0), "+f"(c1), "+f"(c2), "+f"(c3)
        : "r"(a0), "r"(a1), "r"(a2), "r"(a3), "r"(b0), "r"(b1));
}

// Exact distance, R1's PROVEN accumulation: sequential fmaf chain j=0..63,
// then fmaf(-2, dot, base). Matched reference argmin bit-for-bit.
__device__ __forceinline__ float exact_dist(const float* __restrict__ xrow,
                                            const float* __restrict__ wrow,
                                            float base) {
    float dot = 0.f;
    #pragma unroll
    for (int j = 0; j < DIM; ++j)
        dot = fmaf(wrow[j], xrow[j], dot);
    return fmaf(-2.f, dot, base);
}

// Warp-aggregated queue append.
__device__ __forceinline__ void queue_append(
    int cond, uint32_t entry, int* qcount, uint32_t* queue,
    const float* xrow, const float* wrow_g, float base, uint32_t gcode,
    unsigned long long* bestp)
{
    unsigned m = __ballot_sync(0xffffffffu, cond);
    if (cond) {
        int lane   = threadIdx.x & 31;
        int leader = __ffs(m) - 1;
        int rank   = __popc(m & ((1u << lane) - 1u));
        int basep  = 0;
        if (lane == leader) basep = atomicAdd(qcount, __popc(m));
        basep = __shfl_sync(m, basep, leader);
        int slot = basep + rank;
        if (slot < QCAP) {
            queue[slot] = entry;
        } else {                         // overflow (statistically never)
            float d = exact_dist(xrow, wrow_g, base);
            unsigned long long key =
                ((unsigned long long)__float_as_uint(d) << 32) | gcode;
            atomicMin(bestp, key);
        }
    }
}

// ---------------------------------------------------------------------------
// Kernel 0: wsq + zero counts + fp16 codebook
// ---------------------------------------------------------------------------
__global__ void vq_prep(const float* __restrict__ W) {
    int k = blockIdx.x * blockDim.x + threadIdx.x;
    if (k < KCODES) {
        const float* row = W + (size_t)k * DIM;
        float s = 0.f;
        #pragma unroll
        for (int j = 0; j < DIM; ++j) {
            float v = row[j];
            s += v * v;
            g_wh[k * DIM + j] = __float2half_rn(v);
        }
        g_wsq[k]    = s;
        g_counts[k] = 0;
    }
}

// ---------------------------------------------------------------------------
// Kernel 1: fp16 HMMA screen (branchless) + queued exact fp32 refine
// ---------------------------------------------------------------------------
__global__ void __launch_bounds__(NTHREADS, 2)
vq_main(const float* __restrict__ x, const float* __restrict__ W,
        float* __restrict__ out)
{
    extern __shared__ float sf[];
    float*    xs    = sf + OFF_XS;                    // [128][68] fp32
    __half*   wh    = (__half*)(sf + OFF_WH);         // [2][64][72] fp16
    float*    wsq_s = sf + OFF_WSQ;
    float*    xsq_s = sf + OFF_XSQ;
    unsigned long long* best = (unsigned long long*)(sf + OFF_BEST);
    int*      qcount = (int*)(sf + OFF_QCNT);
    uint32_t* queue  = (uint32_t*)(sf + OFF_QUEUE);
    int*      fidx   = (int*)(sf + OFF_FIDX);
    float*    red    = sf + OFF_RED;

    const int tid   = threadIdx.x;
    const int wid   = tid >> 5;
    const int lane  = tid & 31;
    const int qr    = lane >> 2;     // 0..7
    const int qc    = lane & 3;      // 0..3
    const int tbase = blockIdx.x * TT;

    const uint32_t wh_u = smem_u32(wh);

    if (tid == 0) *qcount = 0;
    if (tid < TT) best[tid] = 0xFFFFFFFFFFFFFFFFull;

    // ---- load X tile (fp32, padded) ----
    for (int i = tid; i < TT * 16; i += NTHREADS) {
        int t  = i >> 4;
        int c4 = (i & 15) << 2;
        float4 v = *(const float4*)(x + (size_t)(tbase + t) * DIM + c4);
        *(float4*)(xs + t * XSTR + c4) = v;
    }
    for (int i = tid; i < KCODES; i += NTHREADS) wsq_s[i] = g_wsq[i];

    // ---- prefetch fp16 W chunk 0 (8 x 16B segments per code row) ----
    for (int i = tid; i < CH * 8; i += NTHREADS) {
        int r = i >> 3, seg = i & 7;
        CP_ASYNC16(wh_u + (uint32_t)(r * WHSTR * 2 + seg * 16),
                   g_wh + (size_t)r * DIM + seg * 8);
    }
    CP_COMMIT();
    __syncthreads();

    // ---- xsq per token (sequential, as R1/reference) ----
    if (tid < TT) {
        const float* row = xs + tid * XSTR;
        float s = 0.f;
        #pragma unroll
        for (int j = 0; j < DIM; ++j) { float v = row[j]; s += v * v; }
        xsq_s[tid] = s;
    }
    __syncthreads();

    // ---- A fragments (fp16): 16 tokens/warp, K=64 -> 4 k-steps ----
    const int t0 = wid * 16 + qr;
    const float* xrow0 = xs + t0 * XSTR;
    const float* xrow1 = xs + (t0 + 8) * XSTR;
    uint32_t a[4][4];
    #pragma unroll
    for (int ki = 0; ki < 4; ++ki) {
        int kb = ki * 16 + 2 * qc;
        a[ki][0] = f2_to_h2_bits(xrow0[kb],     xrow0[kb + 1]);
        a[ki][1] = f2_to_h2_bits(xrow1[kb],     xrow1[kb + 1]);
        a[ki][2] = f2_to_h2_bits(xrow0[kb + 8], xrow0[kb + 9]);
        a[ki][3] = f2_to_h2_bits(xrow1[kb + 8], xrow1[kb + 9]);
    }
    const float xsq0 = xsq_s[t0];
    const float xsq1 = xsq_s[t0 + 8];

    float rlb0 = 3.0e38f, rlb1 = 3.0e38f;   // running local APPROX minima

    for (int c = 0; c < NCH; ++c) {
        const int b = c & 1;
        CP_WAIT0();
        __syncthreads();                 // chunk c resident; qcount reset

        if (c + 1 < NCH) {               // prefetch next fp16 chunk
            const __half* src = g_wh + (size_t)(c + 1) * CH * DIM;
            const uint32_t dst0 = wh_u + (uint32_t)(((c + 1) & 1) * CH * WHSTR * 2);
            for (int i = tid; i < CH * 8; i += NTHREADS) {
                int r = i >> 3, seg = i & 7;
                CP_ASYNC16(dst0 + (uint32_t)(r * WHSTR * 2 + seg * 16),
                           src + (size_t)r * DIM + seg * 8);
            }
            CP_COMMIT();
        }

        const uint32_t* whb = (const uint32_t*)(wh + b * CH * WHSTR);

        #pragma unroll
        for (int tile = 0; tile < CH / 8; ++tile) {
            // B frags: code n = tile*8 + qr, k pairs {2qc,2qc+1} and {+8,+9}
            const uint32_t* brow = whb + (tile * 8 + qr) * (WHSTR / 2) + qc;
            float c0 = 0.f, c1 = 0.f, c2 = 0.f, c3 = 0.f;
            #pragma unroll
            for (int ki = 0; ki < 4; ++ki) {
                uint32_t b0 = brow[ki * 8];
                uint32_t b1 = brow[ki * 8 + 4];
                mma_f16(c0, c1, c2, c3, a[ki][0], a[ki][1], a[ki][2], a[ki][3], b0, b1);
            }
            const int lc0 = tile * 8 + 2 * qc;       // local code (D cols 2qc,2qc+1)
            const int g0  = c * CH + lc0;
            const int g1  = g0 + 1;
            const float base00 = wsq_s[g0] + xsq0;
            const float base10 = wsq_s[g1] + xsq0;
            const float base01 = wsq_s[g0] + xsq1;
            const float base11 = wsq_s[g1] + xsq1;
            float a00 = fmaf(-2.f, c0, base00);
            float a10 = fmaf(-2.f, c1, base10);
            float a01 = fmaf(-2.f, c2, base01);
            float a11 = fmaf(-2.f, c3, base11);

            queue_append(a00 < rlb0 + MARGIN, (uint32_t)((t0 << 8) | lc0),
                         qcount, queue, xrow0, W + (size_t)g0 * DIM, base00,
                         (uint32_t)g0, &best[t0]);
            queue_append(a10 < rlb0 + MARGIN, (uint32_t)((t0 << 8) | (lc0 + 1)),
                         qcount, queue, xrow0, W + (size_t)g1 * DIM, base10,
                         (uint32_t)g1, &best[t0]);
            queue_append(a01 < rlb1 + MARGIN, (uint32_t)(((t0 + 8) << 8) | lc0),
                         qcount, queue, xrow1, W + (size_t)g0 * DIM, base01,
                         (uint32_t)g0, &best[t0 + 8]);
            queue_append(a11 < rlb1 + MARGIN, (uint32_t)(((t0 + 8) << 8) | (lc0 + 1)),
                         qcount, queue, xrow1, W + (size_t)g1 * DIM, base11,
                         (uint32_t)g1, &best[t0 + 8]);

            rlb0 = fminf(rlb0, fminf(a00, a10));
            rlb1 = fminf(rlb1, fminf(a01, a11));
        }

        __syncthreads();                 // appends visible

        // ---- cooperative exact refine (fp32 W from global/L2) ----
        const int n = *qcount;
        const int nq = n < QCAP ? n : QCAP;
        for (int i = tid; i < nq; i += NTHREADS) {
            uint32_t e = queue[i];
            int t  = (int)(e >> 8);
            int lc = (int)(e & 255);
            int g  = c * CH + lc;
            float base = wsq_s[g] + xsq_s[t];
            float d = exact_dist(xs + t * XSTR, W + (size_t)g * DIM, base);
            unsigned long long key =
                ((unsigned long long)__float_as_uint(d) << 32) | (uint32_t)g;
            atomicMin(&best[t], key);
        }

        __syncthreads();                 // refine done
        if (tid == 0) *qcount = 0;
    }

    __syncthreads();
    if (tid < TT) {
        int bi = (int)(best[tid] & 0xFFFFFFFFull);
        fidx[tid] = bi;
        atomicAdd(&g_counts[bi], 1);
    }
    __syncthreads();

    // ---- epilogue: quantized_st (coalesced) + loss partial ----
    float ls = 0.f;
    for (int i = tid; i < TT * 16; i += NTHREADS) {
        int t  = i >> 4;
        int c4 = (i & 15) << 2;
        int kb = fidx[t];
        float4 w4 = *(const float4*)(W + (size_t)kb * DIM + c4);
        float4 xv = *(const float4*)(xs + t * XSTR + c4);
        float4 o; float dq;
        dq = w4.x - xv.x; o.x = xv.x + dq; ls = fmaf(dq, dq, ls);
        dq = w4.y - xv.y; o.y = xv.y + dq; ls = fmaf(dq, dq, ls);
        dq = w4.z - xv.z; o.z = xv.z + dq; ls = fmaf(dq, dq, ls);
        dq = w4.w - xv.w; o.w = xv.w + dq; ls = fmaf(dq, dq, ls);
        *(float4*)(out + (size_t)(tbase + t) * DIM + c4) = o;
    }

    red[tid] = ls;
    __syncthreads();
    for (int off = NTHREADS / 2; off > 0; off >>= 1) {
        if (tid < off) red[tid] += red[tid + off];
        __syncthreads();
    }
    if (tid == 0) g_part[blockIdx.x] = red[0];
}

// ---------------------------------------------------------------------------
// Kernel 2: final scalars (loss, perplexity, usage)
// ---------------------------------------------------------------------------
__global__ void vq_final(float* __restrict__ out, int out_size) {
    __shared__ float red[1024];
    __shared__ float red2[1024];
    int tid = threadIdx.x;

    red[tid] = g_part[tid];
    __syncthreads();
    for (int off = 512; off > 0; off >>= 1) {
        if (tid < off) red[tid] += red[tid + off];
        __syncthreads();
    }
    float sse = red[0];
    __syncthreads();

    int c  = g_counts[tid];
    float p = (float)c / (float)N_TOK;
    red[tid]  = p * logf(p + 1e-10f);
    red2[tid] = (c >= 1) ? 1.f : 0.f;
    __syncthreads();
    for (int off = 512; off > 0; off >>= 1) {
        if (tid < off) { red[tid] += red[tid + off]; red2[tid] += red2[tid + off]; }
        __syncthreads();
    }
    if (tid == 0 && out_size >= N_TOK * DIM + 3) {
        float mse = sse / (float)(N_TOK * DIM);
        out[N_TOK * DIM + 0] = mse + 2.0f * mse;   // q_latent + COMMITMENT_COST*e_latent
        out[N_TOK * DIM + 1] = expf(-red[0]);
        out[N_TOK * DIM + 2] = red2[0];
    }
}

// ---------------------------------------------------------------------------
extern "C" void kernel_launch(void* const* d_in, const int* in_sizes, int n_in,
                              void* d_out, int out_size) {
    const float* x = (const float*)d_in[0];   // [32,4096,64] f32
    const float* W = (const float*)d_in[1];   // [1024,64] f32
    float* out = (float*)d_out;

    cudaFuncSetAttribute(vq_main, cudaFuncAttributeMaxDynamicSharedMemorySize,
                         SMEM_BYTES);

    vq_prep<<<8, 128>>>(W);
    vq_main<<<NB, NTHREADS, SMEM_BYTES>>>(x, W, out);
    vq_final<<<1, 1024>>>(out, out_size);
}

// round 10
// speedup vs baseline: 1.8791x; 1.8791x over previous
#include <cuda_runtime.h>
#include <math.h>
#include <stdint.h>

// Problem constants
#define N_TOK   131072      // 32 * 4096 tokens
#define DIM     64
#define KCODES  1024
#define TT      128         // tokens per CTA
#define CK      64          // codes per chunk
#define NCHUNK  (KCODES / CK)   // 16
#define NB      (N_TOK / TT)    // 1024 CTAs
#define NTHREADS 256
#define WT_STR  68          // padded k-stride of transposed W tile

// smem float offsets
#define OFF_XS   0          // xs[64][128] transposed x tile   : 8192
#define OFF_WT   8192       // wsT[2][64][68] transposed W     : 8704
#define OFF_XSQ  16896      // xsq[128]                        : 128
#define SMEM_FLOATS 17024
#define SMEM_BYTES (SMEM_FLOATS * 4)

// Scratch
__device__ float g_wsq[KCODES];
__device__ int   g_counts[KCODES];
__device__ float g_part[NB];

// ---- packed f32x2 helpers (PTX baseline sm_100-family; NOT 'a'-suffix) ----
__device__ __forceinline__ void fma2(unsigned long long& acc,
                                     unsigned long long w2,
                                     unsigned long long x2) {
    asm("fma.rn.f32x2 %0, %1, %2, %0;" : "+l"(acc) : "l"(w2), "l"(x2));
}
__device__ __forceinline__ unsigned long long dup2(float v) {
    unsigned long long r;
    asm("mov.b64 %0, {%1, %1};" : "=l"(r) : "f"(v));
    return r;
}
__device__ __forceinline__ void unpack2(unsigned long long a, float& lo, float& hi) {
    asm("mov.b64 {%0, %1}, %2;" : "=f"(lo), "=f"(hi) : "l"(a));
}

// ---------------------------------------------------------------------------
// Kernel 0: wsq[k] = sum_j W[k][j]^2 (sequential), zero counts
// ---------------------------------------------------------------------------
__global__ void vq_prep(const float* __restrict__ W) {
    int k = blockIdx.x * blockDim.x + threadIdx.x;
    if (k < KCODES) {
        const float* row = W + (size_t)k * DIM;
        float s = 0.f;
        #pragma unroll
        for (int j = 0; j < DIM; ++j) s += row[j] * row[j];
        g_wsq[k]    = s;
        g_counts[k] = 0;
    }
}

// ---------------------------------------------------------------------------
// Kernel 1: packed-f32x2 distance GEMM + argmin + quantize + loss + counts
//   256 thr (8 warps). Tokens on lanes (4/thread), codes on warps (8/warp,
//   held as 4 packed pairs). W chunk transposed in smem so code pairs are
//   contiguous (broadcast LDS). Bit-identical accumulation to R1.
// ---------------------------------------------------------------------------
__global__ void __launch_bounds__(NTHREADS, 2)
vq_main(const float* __restrict__ x, const float* __restrict__ W,
        float* __restrict__ out)
{
    extern __shared__ float sf[];
    float* xs  = sf + OFF_XS;                 // [j][t]
    float* wsT = sf + OFF_WT;                 // [2][j][k] padded
    float* xsq = sf + OFF_XSQ;
    // union region (valid after mainloop's final __syncthreads):
    float* bd   = wsT;                        // [8][128]
    int*   bi   = (int*)(wsT + 1024);         // [8][128]
    int*   fidx = (int*)(wsT + 2048);         // [128]
    float* red  = wsT;                        // loss reduce (after argmin)

    const int tid  = threadIdx.x;
    const int wid  = tid >> 5;
    const int lane = tid & 31;
    const int tbase = blockIdx.x * TT;
    const int t0 = lane * 4;                  // this thread's 4 tokens
    const int k0 = wid * 8;                   // this warp's 8 codes (4 pairs)

    // ---- load x tile transposed ----
    for (int i = tid; i < TT * 16; i += NTHREADS) {
        int t  = i >> 4;
        int j4 = (i & 15) << 2;
        float4 v = *(const float4*)(x + (size_t)(tbase + t) * DIM + j4);
        xs[(j4 + 0) * TT + t] = v.x;
        xs[(j4 + 1) * TT + t] = v.y;
        xs[(j4 + 2) * TT + t] = v.z;
        xs[(j4 + 3) * TT + t] = v.w;
    }
    // ---- load W chunk 0 transposed into buffer 0 ----
    for (int i = tid; i < CK * 16; i += NTHREADS) {
        int r = i >> 4, c4 = (i & 15) << 2;
        float4 v = *(const float4*)(W + (size_t)r * DIM + c4);
        wsT[(c4 + 0) * WT_STR + r] = v.x;
        wsT[(c4 + 1) * WT_STR + r] = v.y;
        wsT[(c4 + 2) * WT_STR + r] = v.z;
        wsT[(c4 + 3) * WT_STR + r] = v.w;
    }
    __syncthreads();

    // ---- xsq per token (sequential j, as reference/R1) ----
    if (tid < TT) {
        float s = 0.f;
        for (int j = 0; j < DIM; ++j) { float v = xs[j * TT + tid]; s += v * v; }
        xsq[tid] = s;
    }
    __syncthreads();
    float xsqr[4];
    #pragma unroll
    for (int c = 0; c < 4; ++c) xsqr[c] = xsq[t0 + c];

    float bestd[4]; int besti[4];
    #pragma unroll
    for (int c = 0; c < 4; ++c) { bestd[c] = 3.0e38f; besti[c] = 0; }

    for (int ch = 0; ch < NCHUNK; ++ch) {
        const int b = ch & 1;

        // register-prefetch next chunk (latency hidden behind compute)
        float4 pf[4];
        if (ch + 1 < NCHUNK) {
            const float* src = W + (size_t)(ch + 1) * CK * DIM;
            #pragma unroll
            for (int q = 0; q < 4; ++q) {
                int i = tid + q * NTHREADS;
                int r = i >> 4, c4 = (i & 15) << 2;
                pf[q] = *(const float4*)(src + (size_t)r * DIM + c4);
            }
        }

        const float* wb = wsT + b * (CK * WT_STR) + k0;

        unsigned long long acc[4][4];     // [token][code-pair]
        #pragma unroll
        for (int c = 0; c < 4; ++c)
            #pragma unroll
            for (int p = 0; p < 4; ++p) acc[c][p] = 0ull;

        #pragma unroll 4
        for (int j = 0; j < DIM; ++j) {
            float4 xq = *(const float4*)(xs + j * TT + t0);
            const ulonglong2* wp = (const ulonglong2*)(wb + j * WT_STR);
            ulonglong2 wA = wp[0];        // code pairs 0,1 (broadcast)
            ulonglong2 wB = wp[1];        // code pairs 2,3
            unsigned long long xx;
            xx = dup2(xq.x);
            fma2(acc[0][0], wA.x, xx); fma2(acc[0][1], wA.y, xx);
            fma2(acc[0][2], wB.x, xx); fma2(acc[0][3], wB.y, xx);
            xx = dup2(xq.y);
            fma2(acc[1][0], wA.x, xx); fma2(acc[1][1], wA.y, xx);
            fma2(acc[1][2], wB.x, xx); fma2(acc[1][3], wB.y, xx);
            xx = dup2(xq.z);
            fma2(acc[2][0], wA.x, xx); fma2(acc[2][1], wA.y, xx);
            fma2(acc[2][2], wB.x, xx); fma2(acc[2][3], wB.y, xx);
            xx = dup2(xq.w);
            fma2(acc[3][0], wA.x, xx); fma2(acc[3][1], wA.y, xx);
            fma2(acc[3][2], wB.x, xx); fma2(acc[3][3], wB.y, xx);
        }

        // distances + running argmin (codes ascending -> lowest-index ties)
        const int kg0 = ch * CK + k0;
        #pragma unroll
        for (int p = 0; p < 4; ++p) {
            float wlo = g_wsq[kg0 + 2 * p];
            float whi = g_wsq[kg0 + 2 * p + 1];
            #pragma unroll
            for (int c = 0; c < 4; ++c) {
                float lo, hi;
                unpack2(acc[c][p], lo, hi);
                float d;
                d = fmaf(-2.f, lo, wlo + xsqr[c]);
                if (d < bestd[c]) { bestd[c] = d; besti[c] = kg0 + 2 * p; }
                d = fmaf(-2.f, hi, whi + xsqr[c]);
                if (d < bestd[c]) { bestd[c] = d; besti[c] = kg0 + 2 * p + 1; }
            }
        }

        // store prefetched chunk into other buffer (transposed)
        if (ch + 1 < NCHUNK) {
            float* dst = wsT + (b ^ 1) * (CK * WT_STR);
            #pragma unroll
            for (int q = 0; q < 4; ++q) {
                int i = tid + q * NTHREADS;
                int r = i >> 4, c4 = (i & 15) << 2;
                dst[(c4 + 0) * WT_STR + r] = pf[q].x;
                dst[(c4 + 1) * WT_STR + r] = pf[q].y;
                dst[(c4 + 2) * WT_STR + r] = pf[q].z;
                dst[(c4 + 3) * WT_STR + r] = pf[q].w;
            }
        }
        __syncthreads();
    }

    // ---- cross-warp argmin reduction (exact dists, index tie-break) ----
    #pragma unroll
    for (int c = 0; c < 4; ++c) {
        bd[wid * TT + t0 + c] = bestd[c];
        bi[wid * TT + t0 + c] = besti[c];
    }
    __syncthreads();
    if (tid < TT) {
        float bdv = bd[tid]; int biv = bi[tid];
        #pragma unroll
        for (int w = 1; w < 8; ++w) {
            float d2 = bd[w * TT + tid]; int i2 = bi[w * TT + tid];
            if (d2 < bdv || (d2 == bdv && i2 < biv)) { bdv = d2; biv = i2; }
        }
        fidx[tid] = biv;
        atomicAdd(&g_counts[biv], 1);
    }
    __syncthreads();

    // ---- epilogue: quantized_st + loss partial (as R1) ----
    float ls = 0.f;
    for (int s = tid; s < TT * 2; s += NTHREADS) {
        int t  = s >> 1;
        int j0 = (s & 1) * 32;
        int kb = fidx[t];
        const float* wrow = W + (size_t)kb * DIM + j0;
        float* orow = out + (size_t)(tbase + t) * DIM + j0;
        #pragma unroll
        for (int jj = 0; jj < 32; jj += 4) {
            float4 w4 = *(const float4*)(wrow + jj);
            float4 o;
            float xv, dq;
            xv = xs[(j0 + jj + 0) * TT + t]; dq = w4.x - xv; o.x = xv + dq; ls = fmaf(dq, dq, ls);
            xv = xs[(j0 + jj + 1) * TT + t]; dq = w4.y - xv; o.y = xv + dq; ls = fmaf(dq, dq, ls);
            xv = xs[(j0 + jj + 2) * TT + t]; dq = w4.z - xv; o.z = xv + dq; ls = fmaf(dq, dq, ls);
            xv = xs[(j0 + jj + 3) * TT + t]; dq = w4.w - xv; o.w = xv + dq; ls = fmaf(dq, dq, ls);
            *(float4*)(orow + jj) = o;
        }
    }

    __syncthreads();
    red[tid] = ls;
    __syncthreads();
    for (int off = NTHREADS / 2; off > 0; off >>= 1) {
        if (tid < off) red[tid] += red[tid + off];
        __syncthreads();
    }
    if (tid == 0) g_part[blockIdx.x] = red[0];
}

// ---------------------------------------------------------------------------
// Kernel 2: final scalars (loss, perplexity, usage)
// ---------------------------------------------------------------------------
__global__ void vq_final(float* __restrict__ out, int out_size) {
    __shared__ float red[1024];
    __shared__ float red2[1024];
    int tid = threadIdx.x;

    red[tid] = g_part[tid];
    __syncthreads();
    for (int off = 512; off > 0; off >>= 1) {
        if (tid < off) red[tid] += red[tid + off];
        __syncthreads();
    }
    float sse = red[0];
    __syncthreads();

    int c  = g_counts[tid];
    float p = (float)c / (float)N_TOK;
    red[tid]  = p * logf(p + 1e-10f);
    red2[tid] = (c >= 1) ? 1.f : 0.f;
    __syncthreads();
    for (int off = 512; off > 0; off >>= 1) {
        if (tid < off) { red[tid] += red[tid + off]; red2[tid] += red2[tid + off]; }
        __syncthreads();
    }
    if (tid == 0 && out_size >= N_TOK * DIM + 3) {
        float mse = sse / (float)(N_TOK * DIM);
        out[N_TOK * DIM + 0] = mse + 2.0f * mse;   // q_latent + COMMITMENT_COST*e_latent
        out[N_TOK * DIM + 1] = expf(-red[0]);
        out[N_TOK * DIM + 2] = red2[0];
    }
}

// ---------------------------------------------------------------------------
extern "C" void kernel_launch(void* const* d_in, const int* in_sizes, int n_in,
                              void* d_out, int out_size) {
    const float* x = (const float*)d_in[0];   // [32,4096,64] f32
    const float* W = (const float*)d_in[1];   // [1024,64] f32
    float* out = (float*)d_out;

    cudaFuncSetAttribute(vq_main, cudaFuncAttributeMaxDynamicSharedMemorySize,
                         SMEM_BYTES);

    vq_prep<<<8, 128>>>(W);
    vq_main<<<NB, NTHREADS, SMEM_BYTES>>>(x, W, out);
    vq_final<<<1, 1024>>>(out, out_size);
}